// round 3
// baseline (speedup 1.0000x reference)
#include <cuda_runtime.h>
#include <cstdint>
#include <cstddef>

#define B   32
#define T   2048
#define E   512
#define H   512
#define G4  2048
#define NCTA 128
#define RTHREADS 256
#define HS_STRIDE  516   // floats per row (512 + 4 pad)
#define HS_STRIDE4 129   // float4 units per row

typedef unsigned long long ull;

// ---- device scratch ----
__device__ float g_xg[(size_t)B * T * G4];        // precomputed x@Wx + bx + bh
__device__ float g_hbuf[2][2][16 * H];            // [group][parity][16 x 512]
__device__ unsigned g_bar[2];                     // per-group arrival counters

// ---- packed f32x2 helpers ----
__device__ __forceinline__ ull pk2(float x, float y) {
    ull r; asm("mov.b64 %0, {%1, %2};" : "=l"(r) : "f"(x), "f"(y)); return r;
}
__device__ __forceinline__ ull ffma2(ull a, ull b, ull c) {
    ull d; asm("fma.rn.f32x2 %0, %1, %2, %3;" : "=l"(d) : "l"(a), "l"(b), "l"(c));
    return d;
}
__device__ __forceinline__ void unpk(ull v, float& lo, float& hi) {
    asm("mov.b64 {%0, %1}, %2;" : "=f"(lo), "=f"(hi) : "l"(v));
}
__device__ __forceinline__ float psum(ull v) {
    float lo, hi; unpk(v, lo, hi); return lo + hi;
}
__device__ __forceinline__ float sigm(float x) {
    return 1.f / (1.f + __expf(-x));
}
__device__ __forceinline__ float tanh_fast(float x) {
    return 2.f / (1.f + __expf(-2.f * x)) - 1.f;
}

__global__ void reset_bar_kernel() { g_bar[0] = 0; g_bar[1] = 0; }

// =====================================================================
// Kernel 1: xg = X@Wx + bx + bh.  128x128 tile, 8x8/thread, FFMA2 inner.
// =====================================================================
__global__ __launch_bounds__(256) void xg_gemm_kernel(
    const float* __restrict__ X, const float* __restrict__ Wx,
    const float* __restrict__ bx, const float* __restrict__ bh)
{
    __shared__ float As[8][128];
    __shared__ float Bs[8][132];
    const int tid = threadIdx.x;
    const int mBase = blockIdx.y * 128;
    const int nBase = blockIdx.x * 128;
    const int arow = tid >> 1, acol = (tid & 1) * 4;
    const int brow = tid >> 5, bcol = (tid & 31) * 4;
    const int tm = (tid >> 4) * 8;
    const int tn = (tid & 15) * 8;

    ull acc2[8][4];
    #pragma unroll
    for (int i = 0; i < 8; i++)
        #pragma unroll
        for (int j = 0; j < 4; j++) acc2[i][j] = 0ULL;

    const float* Aptr = X  + (size_t)(mBase + arow) * E + acol;
    const float* Bptr = Wx + (size_t)brow * G4 + nBase + bcol;

    for (int k0 = 0; k0 < E; k0 += 8) {
        float4 av = *(const float4*)(Aptr + k0);
        float4 bv = *(const float4*)(Bptr + (size_t)k0 * G4);
        __syncthreads();
        As[acol + 0][arow] = av.x;
        As[acol + 1][arow] = av.y;
        As[acol + 2][arow] = av.z;
        As[acol + 3][arow] = av.w;
        *(float4*)&Bs[brow][bcol] = bv;
        __syncthreads();
        #pragma unroll
        for (int k = 0; k < 8; k++) {
            float4 a0 = *(const float4*)&As[k][tm];
            float4 a1 = *(const float4*)&As[k][tm + 4];
            float4 b0 = *(const float4*)&Bs[k][tn];
            float4 b1 = *(const float4*)&Bs[k][tn + 4];
            ull bp[4] = { pk2(b0.x, b0.y), pk2(b0.z, b0.w),
                          pk2(b1.x, b1.y), pk2(b1.z, b1.w) };
            float aa[8] = { a0.x, a0.y, a0.z, a0.w, a1.x, a1.y, a1.z, a1.w };
            #pragma unroll
            for (int i = 0; i < 8; i++) {
                ull ad = pk2(aa[i], aa[i]);
                #pragma unroll
                for (int j = 0; j < 4; j++)
                    acc2[i][j] = ffma2(ad, bp[j], acc2[i][j]);
            }
        }
    }

    float bsum[8];
    #pragma unroll
    for (int j = 0; j < 8; j++)
        bsum[j] = bx[nBase + tn + j] + bh[nBase + tn + j];

    #pragma unroll
    for (int i = 0; i < 8; i++) {
        float r[8];
        #pragma unroll
        for (int j = 0; j < 4; j++) unpk(acc2[i][j], r[2 * j], r[2 * j + 1]);
        size_t row = (size_t)(mBase + tm + i);
        float4 v0 = make_float4(r[0] + bsum[0], r[1] + bsum[1],
                                r[2] + bsum[2], r[3] + bsum[3]);
        float4 v1 = make_float4(r[4] + bsum[4], r[5] + bsum[5],
                                r[6] + bsum[6], r[7] + bsum[7]);
        *(float4*)&g_xg[row * G4 + nBase + tn]     = v0;
        *(float4*)&g_xg[row * G4 + nBase + tn + 4] = v1;
    }
}

// =====================================================================
// Kernel 2: persistent LSTM recurrence, 2-group batch pipeline.
// 128 CTAs x 256 thr. CTA owns 4 hidden units (16 gate columns).
// Tick (t,g): gates for batches [g*16, g*16+16).
// Mainloop: warp w covers k in [w*64, w*64+64); lane tile 2b x 4c, FFMA2
// packed along k (float4 halves -> natural aligned register pairs).
// Deferred grid barrier: arrive at end of tick, wait at next same-group
// tick, so the other group's compute hides barrier + L2 broadcast.
// =====================================================================
__global__ __launch_bounds__(RTHREADS, 1) void lstm_rec_kernel(
    const float* __restrict__ Wh, float* __restrict__ out)
{
    extern __shared__ float sm[];
    float*  whs  = sm;                               // 16 x 516
    float*  hsf  = sm + 16 * HS_STRIDE;              // 32 x 516 (A rows 0-15, B 16-31)
    float4* red4 = (float4*)(hsf + 32 * HS_STRIDE);  // [2][512] float4

    const int tid  = threadIdx.x;
    const int lane = tid & 31;
    const int w    = tid >> 5;
    const int cta  = blockIdx.x;

    // Wh slice: whs[c][k] = Wh[k][(c>>2)*512 + cta*4 + (c&3)]
    for (int idx = tid; idx < 16 * 512; idx += RTHREADS) {
        int c = idx >> 9;
        int k = idx & 511;
        int col = ((c >> 2) << 9) + cta * 4 + (c & 3);
        whs[c * HS_STRIDE + k] = Wh[(size_t)k * G4 + col];
    }
    for (int idx = tid; idx < 32 * HS_STRIDE; idx += RTHREADS) hsf[idx] = 0.f;

    const int lb = lane & 7;    // batch-in-group = lb + 8j, j in {0,1}
    const int lc = lane >> 3;   // local hidden 0..3
    const float4* whs4 = (const float4*)whs;
    const float4* hs4c = (const float4*)hsf;
    float4*       hs4w = (float4*)hsf;

    // Reducer identity (tid < 64): rj in {0,1}
    const int rj   = tid >> 5;
    const int rBl  = (lane & 7) + 8 * rj;       // batch in group, 0..15
    const int hid  = cta * 4 + (lane >> 3);     // global hidden index
    float cst[2] = {0.f, 0.f};                  // c state per group

    __syncthreads();

    for (int t = 0; t < T; t++) {
        #pragma unroll
        for (int g = 0; g < 2; g++) {
            // ---- wait for this group's previous broadcast, reload h ----
            if (t > 0) {
                if (tid == 0) {
                    unsigned target = (unsigned)NCTA * (unsigned)t;
                    while (*(volatile unsigned*)&g_bar[g] < target) { }
                }
                __syncthreads();
            }
            // xg prefetch for epilogue (independent of smem)
            float xp0 = 0.f, xp1 = 0.f, xp2 = 0.f, xp3 = 0.f;
            if (tid < 64) {
                const float* xr =
                    g_xg + ((size_t)(g * 16 + rBl) * T + t) * G4 + hid;
                xp0 = __ldcs(xr);
                xp1 = __ldcs(xr + 512);
                xp2 = __ldcs(xr + 1024);
                xp3 = __ldcs(xr + 1536);
            }
            if (t > 0) {
                const float4* src = (const float4*)g_hbuf[g][t & 1];
                #pragma unroll
                for (int q = 0; q < 8; q++) {
                    int v  = tid + RTHREADS * q;   // 0..2047
                    int b  = v >> 7;
                    int kk = v & 127;
                    hs4w[(g * 16 + b) * HS_STRIDE4 + kk] = __ldcg(src + v);
                }
                __syncthreads();
            }

            // ---- mainloop: packed-k FFMA2 partial dot products ----
            ull acc2[2][4];
            #pragma unroll
            for (int j = 0; j < 2; j++)
                #pragma unroll
                for (int i = 0; i < 4; i++) acc2[j][i] = 0ULL;

            const int kb = w * 16;
            #pragma unroll 8
            for (int q = 0; q < 16; q++) {
                const int kv = kb + q;
                float4 wv[4];
                #pragma unroll
                for (int i = 0; i < 4; i++)
                    wv[i] = whs4[(lc + 4 * i) * HS_STRIDE4 + kv];
                ull wlo[4], whi[4];
                #pragma unroll
                for (int i = 0; i < 4; i++) {
                    wlo[i] = pk2(wv[i].x, wv[i].y);
                    whi[i] = pk2(wv[i].z, wv[i].w);
                }
                #pragma unroll
                for (int j = 0; j < 2; j++) {
                    float4 hh = hs4c[(g * 16 + lb + 8 * j) * HS_STRIDE4 + kv];
                    ull hlo = pk2(hh.x, hh.y);
                    ull hhi = pk2(hh.z, hh.w);
                    #pragma unroll
                    for (int i = 0; i < 4; i++) {
                        acc2[j][i] = ffma2(hlo, wlo[i], acc2[j][i]);
                        acc2[j][i] = ffma2(hhi, whi[i], acc2[j][i]);
                    }
                }
            }

            // ---- cross-warp k-split reduction (per-group buffer) ----
            float4* redg = red4 + g * 512;
            #pragma unroll
            for (int j = 0; j < 2; j++)
                redg[j * 256 + w * 32 + lane] =
                    make_float4(psum(acc2[j][0]), psum(acc2[j][1]),
                                psum(acc2[j][2]), psum(acc2[j][3]));
            __syncthreads();

            // ---- epilogue: reducer owns (group-batch rBl, hidden hid) ----
            if (tid < 64) {
                float4 s = make_float4(0.f, 0.f, 0.f, 0.f);
                #pragma unroll
                for (int ww = 0; ww < 8; ww++) {
                    float4 v = redg[rj * 256 + ww * 32 + lane];
                    s.x += v.x; s.y += v.y; s.z += v.z; s.w += v.w;
                }
                float f  = sigm(s.x + xp0);
                float ig = sigm(s.y + xp1);
                float cc = tanh_fast(s.z + xp2);
                float og = sigm(s.w + xp3);
                float c_new = f * cst[g] + ig * cc;
                cst[g] = c_new;
                float h_new = og * tanh_fast(c_new);
                g_hbuf[g][(t + 1) & 1][rBl * H + hid] = h_new;
                __threadfence();
                if (t == T - 1) {
                    int gb = g * 16 + rBl;
                    out[gb * H + hid]         = h_new;
                    out[B * H + gb * H + hid] = c_new;
                }
            }
            __syncthreads();
            if (tid == 0) atomicAdd(&g_bar[g], 1u);   // arrive, don't wait
        }
    }
}

// =====================================================================
extern "C" void kernel_launch(void* const* d_in, const int* in_sizes, int n_in,
                              void* d_out, int out_size)
{
    const float* x  = (const float*)d_in[0];
    const float* Wx = (const float*)d_in[1];
    const float* Wh = (const float*)d_in[2];
    const float* bx = (const float*)d_in[3];
    const float* bh = (const float*)d_in[4];
    float* out = (float*)d_out;

    reset_bar_kernel<<<1, 1>>>();

    dim3 g1(G4 / 128, (B * T) / 128);
    xg_gemm_kernel<<<g1, 256>>>(x, Wx, bx, bh);

    const int smem_bytes =
        (16 * HS_STRIDE + 32 * HS_STRIDE + 2 * 512 * 4) * (int)sizeof(float);
    cudaFuncSetAttribute(lstm_rec_kernel,
                         cudaFuncAttributeMaxDynamicSharedMemorySize, smem_bytes);
    lstm_rec_kernel<<<NCTA, RTHREADS, smem_bytes>>>(Wh, out);
}

// round 4
// speedup vs baseline: 1.1357x; 1.1357x over previous
#include <cuda_runtime.h>
#include <cstdint>
#include <cstddef>

#define B   32
#define T   2048
#define E   512
#define H   512
#define G4  2048
#define NCTA 128
#define RTHREADS 256
#define HS_STRIDE  516   // floats per row (512 + 4 pad), 16B-aligned rows
#define HS_STRIDE4 129   // float4 units per row

typedef unsigned long long ull;

// ---- device scratch ----
__device__ float g_xg[(size_t)B * T * G4];   // precomputed x@Wx + bx + bh
__device__ float g_hbuf[2][B * H];           // double-buffered h state
__device__ unsigned g_bar_arrive = 0;
__device__ volatile unsigned g_bar_gen = 0;

// ---- packed f32x2 helpers (no packing movs: operands loaded as u64) ----
__device__ __forceinline__ ull ffma2(ull a, ull b, ull c) {
    ull d; asm("fma.rn.f32x2 %0, %1, %2, %3;" : "=l"(d) : "l"(a), "l"(b), "l"(c));
    return d;
}
__device__ __forceinline__ float psum(ull v) {
    float lo, hi;
    asm("mov.b64 {%0, %1}, %2;" : "=f"(lo), "=f"(hi) : "l"(v));
    return lo + hi;
}
// LDS.128 -> two aligned u64 halves (zero pack cost)
__device__ __forceinline__ void lds_2u64(const float4* p, ull& a, ull& b) {
    unsigned addr = (unsigned)__cvta_generic_to_shared(p);
    asm volatile("ld.shared.v2.u64 {%0, %1}, [%2];"
                 : "=l"(a), "=l"(b) : "r"(addr));
}
__device__ __forceinline__ float sigm(float x) {
    return 1.f / (1.f + __expf(-x));
}
__device__ __forceinline__ float tanh_fast(float x) {
    return 2.f / (1.f + __expf(-2.f * x)) - 1.f;
}

// =====================================================================
// Kernel 1: xg[m][n] = sum_k X[m][k]*Wx[k][n] + bx[n] + bh[n]
// (identical to the round-2 version: known 3.4 ms, fma-pipe bound)
// =====================================================================
__global__ __launch_bounds__(256) void xg_gemm_kernel(
    const float* __restrict__ X, const float* __restrict__ Wx,
    const float* __restrict__ bx, const float* __restrict__ bh)
{
    __shared__ float As[8][128];
    __shared__ float Bs[8][132];
    const int tid = threadIdx.x;
    const int mBase = blockIdx.y * 128;
    const int nBase = blockIdx.x * 128;
    const int arow = tid >> 1, acol = (tid & 1) * 4;
    const int brow = tid >> 5, bcol = (tid & 31) * 4;
    const int tm = (tid >> 4) * 8;
    const int tn = (tid & 15) * 8;

    float acc[8][8];
    #pragma unroll
    for (int i = 0; i < 8; i++)
        #pragma unroll
        for (int j = 0; j < 8; j++) acc[i][j] = 0.f;

    const float* Aptr = X  + (size_t)(mBase + arow) * E + acol;
    const float* Bptr = Wx + (size_t)brow * G4 + nBase + bcol;

    for (int k0 = 0; k0 < E; k0 += 8) {
        float4 av = *(const float4*)(Aptr + k0);
        float4 bv = *(const float4*)(Bptr + (size_t)k0 * G4);
        __syncthreads();
        As[acol + 0][arow] = av.x;
        As[acol + 1][arow] = av.y;
        As[acol + 2][arow] = av.z;
        As[acol + 3][arow] = av.w;
        *(float4*)&Bs[brow][bcol] = bv;
        __syncthreads();
        #pragma unroll
        for (int k = 0; k < 8; k++) {
            float a[8], b[8];
            *(float4*)(a)     = *(const float4*)&As[k][tm];
            *(float4*)(a + 4) = *(const float4*)&As[k][tm + 4];
            *(float4*)(b)     = *(const float4*)&Bs[k][tn];
            *(float4*)(b + 4) = *(const float4*)&Bs[k][tn + 4];
            #pragma unroll
            for (int i = 0; i < 8; i++)
                #pragma unroll
                for (int j = 0; j < 8; j++)
                    acc[i][j] = fmaf(a[i], b[j], acc[i][j]);
        }
    }

    float bsum[8];
    #pragma unroll
    for (int j = 0; j < 8; j++)
        bsum[j] = bx[nBase + tn + j] + bh[nBase + tn + j];

    #pragma unroll
    for (int i = 0; i < 8; i++) {
        size_t row = (size_t)(mBase + tm + i);
        float4 v0 = make_float4(acc[i][0] + bsum[0], acc[i][1] + bsum[1],
                                acc[i][2] + bsum[2], acc[i][3] + bsum[3]);
        float4 v1 = make_float4(acc[i][4] + bsum[4], acc[i][5] + bsum[5],
                                acc[i][6] + bsum[6], acc[i][7] + bsum[7]);
        *(float4*)&g_xg[row * G4 + nBase + tn]     = v0;
        *(float4*)&g_xg[row * G4 + nBase + tn + 4] = v1;
    }
}

// =====================================================================
// Kernel 2: persistent LSTM recurrence (round-2 structure).
// ONE change: mainloop uses fma.rn.f32x2 with operands loaded straight
// from smem as aligned u64 pairs (ld.shared.v2.u64) -> zero pack movs.
// Per-q issue mix: 8 LDS + 32 FFMA2 (was 8 LDS + 64 FFMA).
// =====================================================================
__global__ __launch_bounds__(RTHREADS, 1) void lstm_rec_kernel(
    const float* __restrict__ Wh, float* __restrict__ out)
{
    extern __shared__ float sm[];
    float*  whs  = sm;                               // 16 x 516
    float*  hsf  = sm + 16 * HS_STRIDE;              // 32 x 516
    float4* red4 = (float4*)(hsf + 32 * HS_STRIDE);  // 1024 float4

    const int tid  = threadIdx.x;
    const int lane = tid & 31;
    const int w    = tid >> 5;
    const int cta  = blockIdx.x;

    // Wh slice: whs[c][k] = Wh[k][(c>>2)*512 + cta*4 + (c&3)]
    for (int idx = tid; idx < 16 * 512; idx += RTHREADS) {
        int c = idx >> 9;
        int k = idx & 511;
        int col = ((c >> 2) << 9) + cta * 4 + (c & 3);
        whs[c * HS_STRIDE + k] = Wh[(size_t)k * G4 + col];
    }
    for (int idx = tid; idx < 32 * HS_STRIDE; idx += RTHREADS) hsf[idx] = 0.f;

    unsigned gen = g_bar_gen;

    const int lb = lane & 7;    // b = lb + 8j
    const int lc = lane >> 3;   // c = lc + 4i
    const float4* whs4 = (const float4*)whs;
    const float4* hs4c = (const float4*)hsf;
    float4*       hs4w = (float4*)hsf;

    const int rj  = tid >> 5;                  // 0..3 (reducers tid<128)
    const int rB  = (lane & 7) + 8 * rj;       // batch
    const int hid = cta * 4 + (lane >> 3);     // global hidden index
    float c_state = 0.f;

    __syncthreads();

    for (int t = 0; t < T; t++) {
        // xg prefetch for epilogue
        float xp0 = 0.f, xp1 = 0.f, xp2 = 0.f, xp3 = 0.f;
        if (tid < 128) {
            const float* xr = g_xg + ((size_t)rB * T + t) * G4 + hid;
            xp0 = __ldcs(xr);
            xp1 = __ldcs(xr + 512);
            xp2 = __ldcs(xr + 1024);
            xp3 = __ldcs(xr + 1536);
        }

        // ---- mainloop: packed-k FFMA2, zero-pack u64 smem loads ----
        ull acc2[4][4];
        #pragma unroll
        for (int j = 0; j < 4; j++)
            #pragma unroll
            for (int i = 0; i < 4; i++) acc2[j][i] = 0ULL;

        const int kb = w * 16;
        #pragma unroll 4
        for (int q = 0; q < 16; q++) {
            const int kv = kb + q;
            ull wlo[4], whi[4];
            #pragma unroll
            for (int i = 0; i < 4; i++)
                lds_2u64(&whs4[(lc + 4 * i) * HS_STRIDE4 + kv], wlo[i], whi[i]);
            #pragma unroll
            for (int j = 0; j < 4; j++) {
                ull hlo, hhi;
                lds_2u64(&hs4c[(lb + 8 * j) * HS_STRIDE4 + kv], hlo, hhi);
                #pragma unroll
                for (int i = 0; i < 4; i++) {
                    acc2[j][i] = ffma2(hlo, wlo[i], acc2[j][i]);
                    acc2[j][i] = ffma2(hhi, whi[i], acc2[j][i]);
                }
            }
        }

        // ---- cross-warp (k-split) reduction ----
        __syncthreads();
        #pragma unroll
        for (int j = 0; j < 4; j++)
            red4[j * 256 + w * 32 + lane] =
                make_float4(psum(acc2[j][0]), psum(acc2[j][1]),
                            psum(acc2[j][2]), psum(acc2[j][3]));
        __syncthreads();

        // ---- epilogue ----
        if (tid < 128) {
            float4 s = make_float4(0.f, 0.f, 0.f, 0.f);
            #pragma unroll
            for (int ww = 0; ww < 8; ww++) {
                float4 v = red4[rj * 256 + ww * 32 + lane];
                s.x += v.x; s.y += v.y; s.z += v.z; s.w += v.w;
            }
            float f  = sigm(s.x + xp0);
            float ig = sigm(s.y + xp1);
            float cc = tanh_fast(s.z + xp2);
            float og = sigm(s.w + xp3);
            c_state = f * c_state + ig * cc;
            float h_new = og * tanh_fast(c_state);
            g_hbuf[(t + 1) & 1][rB * H + hid] = h_new;
            if (t == T - 1) {
                out[rB * H + hid]         = h_new;
                out[B * H + rB * H + hid] = c_state;
            }
        }

        // ---- grid-wide barrier ----
        __syncthreads();
        if (tid == 0) {
            __threadfence();
            if (atomicAdd(&g_bar_arrive, 1u) == NCTA - 1) {
                g_bar_arrive = 0;
                __threadfence();
                g_bar_gen = gen + 1;
            } else {
                while (g_bar_gen == gen) { }
                __threadfence();
            }
        }
        __syncthreads();
        gen++;

        // ---- reload full h from L2 ----
        if (t < T - 1) {
            const float4* src = (const float4*)g_hbuf[(t + 1) & 1];
            #pragma unroll
            for (int q = 0; q < 16; q++) {
                int v  = tid + RTHREADS * q;
                int b  = v >> 7;
                int kk = v & 127;
                hs4w[b * HS_STRIDE4 + kk] = __ldcg(src + b * 128 + kk);
            }
            __syncthreads();
        }
    }
}

// =====================================================================
extern "C" void kernel_launch(void* const* d_in, const int* in_sizes, int n_in,
                              void* d_out, int out_size)
{
    const float* x  = (const float*)d_in[0];
    const float* Wx = (const float*)d_in[1];
    const float* Wh = (const float*)d_in[2];
    const float* bx = (const float*)d_in[3];
    const float* bh = (const float*)d_in[4];
    float* out = (float*)d_out;

    dim3 g1(G4 / 128, (B * T) / 128);
    xg_gemm_kernel<<<g1, 256>>>(x, Wx, bx, bh);

    const int smem_bytes =
        (16 * HS_STRIDE + 32 * HS_STRIDE + 4096) * (int)sizeof(float);
    cudaFuncSetAttribute(lstm_rec_kernel,
                         cudaFuncAttributeMaxDynamicSharedMemorySize, smem_bytes);
    lstm_rec_kernel<<<NCTA, RTHREADS, smem_bytes>>>(Wh, out);
}

// round 6
// speedup vs baseline: 1.1559x; 1.0178x over previous
#include <cuda_runtime.h>
#include <cstdint>
#include <cstddef>

#define B   32
#define T   2048
#define E   512
#define H   512
#define G4  2048
#define NCTA 128
#define THREADS 512
#define HS_STRIDE  516   // floats per row (512 + 4 pad)
#define HS_STRIDE4 129   // float4 per row

// ---- device scratch ----
__device__ float g_xg[(size_t)B * T * G4];     // precomputed x@Wx + bx + bh
__device__ float g_hbuf[2][2][16 * H];         // [team][parity][16 x 512]
__device__ unsigned g_bar[2];                  // per-team arrival counters

__device__ __forceinline__ void barn(int id, int cnt) {
    asm volatile("bar.sync %0, %1;" :: "r"(id), "r"(cnt) : "memory");
}
__device__ __forceinline__ unsigned ld_acq(const unsigned* p) {
    unsigned v;
    asm volatile("ld.acquire.gpu.global.u32 %0, [%1];" : "=r"(v) : "l"(p));
    return v;
}
__device__ __forceinline__ float sigm(float x) {
    return 1.f / (1.f + __expf(-x));
}
__device__ __forceinline__ float tanh_fast(float x) {
    return 2.f / (1.f + __expf(-2.f * x)) - 1.f;
}

__global__ void reset_bar_kernel() { g_bar[0] = 0; g_bar[1] = 0; }

// =====================================================================
// Kernel 1: xg = X@Wx + bx + bh (known-good: ~3.4 ms, fma-pipe bound)
// =====================================================================
__global__ __launch_bounds__(256) void xg_gemm_kernel(
    const float* __restrict__ X, const float* __restrict__ Wx,
    const float* __restrict__ bx, const float* __restrict__ bh)
{
    __shared__ float As[8][128];
    __shared__ float Bs[8][132];
    const int tid = threadIdx.x;
    const int mBase = blockIdx.y * 128;
    const int nBase = blockIdx.x * 128;
    const int arow = tid >> 1, acol = (tid & 1) * 4;
    const int brow = tid >> 5, bcol = (tid & 31) * 4;
    const int tm = (tid >> 4) * 8;
    const int tn = (tid & 15) * 8;

    float acc[8][8];
    #pragma unroll
    for (int i = 0; i < 8; i++)
        #pragma unroll
        for (int j = 0; j < 8; j++) acc[i][j] = 0.f;

    const float* Aptr = X  + (size_t)(mBase + arow) * E + acol;
    const float* Bptr = Wx + (size_t)brow * G4 + nBase + bcol;

    for (int k0 = 0; k0 < E; k0 += 8) {
        float4 av = *(const float4*)(Aptr + k0);
        float4 bv = *(const float4*)(Bptr + (size_t)k0 * G4);
        __syncthreads();
        As[acol + 0][arow] = av.x;
        As[acol + 1][arow] = av.y;
        As[acol + 2][arow] = av.z;
        As[acol + 3][arow] = av.w;
        *(float4*)&Bs[brow][bcol] = bv;
        __syncthreads();
        #pragma unroll
        for (int k = 0; k < 8; k++) {
            float a[8], b[8];
            *(float4*)(a)     = *(const float4*)&As[k][tm];
            *(float4*)(a + 4) = *(const float4*)&As[k][tm + 4];
            *(float4*)(b)     = *(const float4*)&Bs[k][tn];
            *(float4*)(b + 4) = *(const float4*)&Bs[k][tn + 4];
            #pragma unroll
            for (int i = 0; i < 8; i++)
                #pragma unroll
                for (int j = 0; j < 8; j++)
                    acc[i][j] = fmaf(a[i], b[j], acc[i][j]);
        }
    }

    float bsum[8];
    #pragma unroll
    for (int j = 0; j < 8; j++)
        bsum[j] = bx[nBase + tn + j] + bh[nBase + tn + j];

    #pragma unroll
    for (int i = 0; i < 8; i++) {
        size_t row = (size_t)(mBase + tm + i);
        float4 v0 = make_float4(acc[i][0] + bsum[0], acc[i][1] + bsum[1],
                                acc[i][2] + bsum[2], acc[i][3] + bsum[3]);
        float4 v1 = make_float4(acc[i][4] + bsum[4], acc[i][5] + bsum[5],
                                acc[i][6] + bsum[6], acc[i][7] + bsum[7]);
        *(float4*)&g_xg[row * G4 + nBase + tn]     = v0;
        *(float4*)&g_xg[row * G4 + nBase + tn + 4] = v1;
    }
}

// =====================================================================
// Kernel 2: persistent recurrence, TWO INDEPENDENT SMT TEAMS.
// 512 threads: team 0 = warps 0-7 (batches 0-15), team 1 = warps 8-15
// (batches 16-31). Each team runs its own 2048-step recurrence with its
// own grid barrier, smem h slot and reduction buffer, synchronized only
// by named barriers. While one team stalls on barrier poll + h reload,
// the other team's 8 warps fill the issue slots.
// CTA owns 4 hidden units (16 gate columns). Within a team: warp w
// covers k-slice [w*64,w*64+64), lane tile 2b x 4gates.
// =====================================================================
__global__ __launch_bounds__(THREADS, 1) void lstm_rec_kernel(
    const float* __restrict__ Wh, float* __restrict__ out)
{
    extern __shared__ float sm[];
    float* whs = sm;                                // 16 x 516 (shared by teams)

    const int tid   = threadIdx.x;
    const int team  = tid >> 8;        // 0 or 1
    const int tt    = tid & 255;       // tid within team
    const int lane  = tid & 31;
    const int wteam = tt >> 5;         // warp index in team, 0..7
    const int cta   = blockIdx.x;

    float*  hslot = sm + (16 + team * 16) * HS_STRIDE;
    float4* redt  = (float4*)(sm + 48 * HS_STRIDE) + team * 512;

    // Wh slice: whs[c][k] = Wh[k][(c>>2)*512 + cta*4 + (c&3)]
    for (int idx = tid; idx < 16 * 512; idx += THREADS) {
        int c = idx >> 9;
        int k = idx & 511;
        int col = ((c >> 2) << 9) + cta * 4 + (c & 3);
        whs[c * HS_STRIDE + k] = Wh[(size_t)k * G4 + col];
    }
    // zero both team h slots
    for (int idx = tid; idx < 32 * HS_STRIDE; idx += THREADS)
        sm[16 * HS_STRIDE + idx] = 0.f;
    __syncthreads();   // only full-CTA sync; teams independent after this

    const int lb = lane & 7;           // batch-in-team = lb + 8j
    const int lc = lane >> 3;          // local hidden 0..3
    const float4* whs4 = (const float4*)whs;
    const float4* hs4  = (const float4*)hslot;
    float4*       hs4w = (float4*)hslot;

    // reducer identity (tt < 64): (batch bl, local hidden hl)
    const int bl    = tt >> 2;                 // 0..15
    const int hl    = tt & 3;                  // 0..3
    const int hid   = cta * 4 + hl;            // global hidden index
    const int bglob = team * 16 + bl;          // global batch
    float c_state = 0.f;

    const int barT = 1 + team;   // team-wide barrier (256 threads)
    const int barR = 3 + team;   // reducer barrier (64 threads)

    for (int t = 0; t < T; t++) {
        // xg prefetch — independent of the barrier, hoisted to hide DRAM lat
        float xp0 = 0.f, xp1 = 0.f, xp2 = 0.f, xp3 = 0.f;
        if (tt < 64) {
            const float* xr = g_xg + ((size_t)bglob * T + t) * G4 + hid;
            xp0 = __ldcs(xr);
            xp1 = __ldcs(xr + 512);
            xp2 = __ldcs(xr + 1024);
            xp3 = __ldcs(xr + 1536);
        }

        if (t > 0) {
            // wait for all CTAs to publish this team's h(t-1)
            if (tt == 0) {
                unsigned target = 128u * (unsigned)t;
                int spins = 0;
                while (ld_acq(&g_bar[team]) < target) {
                    if (++spins > 64) { __nanosleep(64); }   // backoff
                }
            }
            barn(barT, 256);
            // reload team h(t-1): 2048 float4 over 256 threads
            const float4* src = (const float4*)g_hbuf[team][(t - 1) & 1];
            #pragma unroll
            for (int q = 0; q < 8; q++) {
                int v  = tt + 256 * q;
                int b  = v >> 7;
                int kk = v & 127;
                hs4w[b * HS_STRIDE4 + kk] = __ldcg(src + v);
            }
            barn(barT, 256);
        }

        // ---- mainloop: k-slice [wteam*64, +64), 2b x 4gate lane tile ----
        float acc[2][4];
        #pragma unroll
        for (int j = 0; j < 2; j++)
            #pragma unroll
            for (int i = 0; i < 4; i++) acc[j][i] = 0.f;

        const int kb = wteam * 16;
        #pragma unroll 4
        for (int q = 0; q < 16; q++) {
            const int kv = kb + q;
            float4 wv[4];
            #pragma unroll
            for (int i = 0; i < 4; i++)
                wv[i] = whs4[(lc + 4 * i) * HS_STRIDE4 + kv];
            #pragma unroll
            for (int j = 0; j < 2; j++) {
                float4 hh = hs4[(lb + 8 * j) * HS_STRIDE4 + kv];
                #pragma unroll
                for (int i = 0; i < 4; i++) {
                    acc[j][i] = fmaf(hh.x, wv[i].x, acc[j][i]);
                    acc[j][i] = fmaf(hh.y, wv[i].y, acc[j][i]);
                    acc[j][i] = fmaf(hh.z, wv[i].z, acc[j][i]);
                    acc[j][i] = fmaf(hh.w, wv[i].w, acc[j][i]);
                }
            }
        }

        // partials: redt[w*64 + b*4 + hl] = float4 of 4 gates
        #pragma unroll
        for (int j = 0; j < 2; j++)
            redt[wteam * 64 + (lb + 8 * j) * 4 + lc] =
                make_float4(acc[j][0], acc[j][1], acc[j][2], acc[j][3]);
        barn(barT, 256);

        // ---- epilogue: 64 reducers, each owns (bl, hid) ----
        if (tt < 64) {
            float4 s = make_float4(0.f, 0.f, 0.f, 0.f);
            #pragma unroll
            for (int w = 0; w < 8; w++) {
                float4 v = redt[w * 64 + tt];
                s.x += v.x; s.y += v.y; s.z += v.z; s.w += v.w;
            }
            float f  = sigm(s.x + xp0);
            float ig = sigm(s.y + xp1);
            float cc = tanh_fast(s.z + xp2);
            float og = sigm(s.w + xp3);
            c_state = f * c_state + ig * cc;
            float h_new = og * tanh_fast(c_state);
            g_hbuf[team][t & 1][bl * H + hid] = h_new;
            if (t == T - 1) {
                out[bglob * H + hid]         = h_new;
                out[B * H + bglob * H + hid] = c_state;
            }
            barn(barR, 64);
            if (tt == 0) {
                __threadfence();
                atomicAdd(&g_bar[team], 1u);
            }
        }
        // non-reducer warps run ahead to next t's poll barrier
    }
}

// =====================================================================
extern "C" void kernel_launch(void* const* d_in, const int* in_sizes, int n_in,
                              void* d_out, int out_size)
{
    const float* x  = (const float*)d_in[0];
    const float* Wx = (const float*)d_in[1];
    const float* Wh = (const float*)d_in[2];
    const float* bx = (const float*)d_in[3];
    const float* bh = (const float*)d_in[4];
    float* out = (float*)d_out;

    reset_bar_kernel<<<1, 1>>>();

    dim3 g1(G4 / 128, (B * T) / 128);
    xg_gemm_kernel<<<g1, 256>>>(x, Wx, bx, bh);

    const int smem_bytes =
        (48 * HS_STRIDE + 2 * 512 * 4) * (int)sizeof(float);
    cudaFuncSetAttribute(lstm_rec_kernel,
                         cudaFuncAttributeMaxDynamicSharedMemorySize, smem_bytes);
    lstm_rec_kernel<<<NCTA, THREADS, smem_bytes>>>(Wh, out);
}